// round 5
// baseline (speedup 1.0000x reference)
#include <cuda_runtime.h>
#include <math.h>
#include <stdint.h>

#define NB 4096
#define ND 128
#define NM 8192
#define NK 4
#define NBD (NB*ND)   /* 524288 */

/* ------------------------------------------------------------------ */
/* device scratch (static: allocation rules forbid cudaMalloc)         */
/* ------------------------------------------------------------------ */
__device__ float g_res[2*NBD];          /* residuals pcf/plm            */
__device__ float g_q[2*NBD];            /* quantized accumulators       */
__device__ float g_normX[2*NB];
__device__ float g_normE[NK*NM];
__device__ float g_dist[2*NB*NM];       /* 256 MB: [2][B][M]            */
__device__ float g_X[NB*2*NM];          /* 256 MB: [B][2M] ph concat    */
__device__ float g_Y[NB*2*NM];          /* 256 MB: [B][2M] logph concat */
__device__ float g_S[NB*NB];            /* 64 MB Scode                  */
__device__ int   g_idx[2*NB];
__device__ float g_cnt[2*NM];
__device__ unsigned g_minord;
__device__ float g_lr;
__device__ float g_mse[4];

/* ------------------------------------------------------------------ */
/* reduction helpers                                                   */
/* ------------------------------------------------------------------ */
__device__ __forceinline__ float blockAllReduceSum(float v){
    __shared__ float sh[33];
    int lane = threadIdx.x & 31, w = threadIdx.x >> 5;
    __syncthreads();
    #pragma unroll
    for (int o=16;o>0;o>>=1) v += __shfl_down_sync(0xffffffffu, v, o);
    if (lane==0) sh[w] = v;
    __syncthreads();
    if (threadIdx.x==0){
        float s = 0.f; int nw = blockDim.x >> 5;
        for (int i=0;i<nw;i++) s += sh[i];
        sh[32] = s;
    }
    __syncthreads();
    return sh[32];
}
__device__ __forceinline__ float blockAllReduceMax(float v){
    __shared__ float sh[33];
    int lane = threadIdx.x & 31, w = threadIdx.x >> 5;
    __syncthreads();
    #pragma unroll
    for (int o=16;o>0;o>>=1) v = fmaxf(v, __shfl_down_sync(0xffffffffu, v, o));
    if (lane==0) sh[w] = v;
    __syncthreads();
    if (threadIdx.x==0){
        float s = -INFINITY; int nw = blockDim.x >> 5;
        for (int i=0;i<nw;i++) s = fmaxf(s, sh[i]);
        sh[32] = s;
    }
    __syncthreads();
    return sh[32];
}

__device__ __forceinline__ unsigned f2ord(float f){
    unsigned u = __float_as_uint(f);
    return (u >> 31) ? ~u : (u | 0x80000000u);
}
__device__ __forceinline__ float ord2f(unsigned o){
    unsigned u = (o >> 31) ? (o ^ 0x80000000u) : ~o;
    return __uint_as_float(u);
}

/* ------------------------------------------------------------------ */
/* kernels                                                             */
/* ------------------------------------------------------------------ */
__global__ void k_init(const float* __restrict__ pcf, const float* __restrict__ plm,
                       float* __restrict__ res, float* __restrict__ q,
                       unsigned* minord, float* lr, float* mse){
    int n = blockIdx.x*blockDim.x + threadIdx.x;
    if (n < 2*NBD){
        res[n] = (n < NBD) ? pcf[n] : plm[n - NBD];
        q[n] = 0.f;
    }
    if (n == 0){
        *minord = 0xFFFFFFFFu; *lr = 0.f;
        mse[0]=0.f; mse[1]=0.f; mse[2]=0.f; mse[3]=0.f;
    }
}

/* one block (128 thr) per row of 128 floats: sum of squares */
__global__ void k_rownorm(const float* __restrict__ x, float* __restrict__ out){
    int r = blockIdx.x;
    float v = x[(size_t)r*ND + threadIdx.x];
    float s = blockAllReduceSum(v*v);
    if (threadIdx.x==0) out[r] = s;
}

/* NT SGEMM: C[i,j] = dot(A_row_i, B_row_j); tile 128x128, K-chunk 16.
   mode=1: dist epilogue  d = (nB[col] + nA[row]) - 2*acc  (matches jnp order) */
__global__ void __launch_bounds__(256, 2) k_gemm(
    const float* __restrict__ A, const float* __restrict__ Bm, float* __restrict__ C,
    int Mr, int Nc, int Kd,
    const float* __restrict__ nA, const float* __restrict__ nB, int mode)
{
    __shared__ float As[16][128];
    __shared__ float Bs[16][128];
    int t = threadIdx.x;
    int tx = t & 15, ty = t >> 4;
    int row0 = blockIdx.y * 128;
    int col0 = blockIdx.x * 128;
    float acc[8][8];
    #pragma unroll
    for (int i=0;i<8;i++)
        #pragma unroll
        for (int j=0;j<8;j++) acc[i][j] = 0.f;

    for (int k0=0; k0<Kd; k0+=16){
        #pragma unroll
        for (int u=0;u<2;u++){
            int l = t*2+u;
            int r = l >> 2;
            int c = (l & 3) << 2;
            float4 va = *(const float4*)(A  + (size_t)(row0 + r)*Kd + k0 + c);
            As[c+0][r]=va.x; As[c+1][r]=va.y; As[c+2][r]=va.z; As[c+3][r]=va.w;
            float4 vb = *(const float4*)(Bm + (size_t)(col0 + r)*Kd + k0 + c);
            Bs[c+0][r]=vb.x; Bs[c+1][r]=vb.y; Bs[c+2][r]=vb.z; Bs[c+3][r]=vb.w;
        }
        __syncthreads();
        #pragma unroll
        for (int kk=0;kk<16;kk++){
            float a[8], b[8];
            #pragma unroll
            for (int i=0;i<8;i++) a[i] = As[kk][ty*8+i];
            #pragma unroll
            for (int j=0;j<8;j++) b[j] = Bs[kk][tx*8+j];
            #pragma unroll
            for (int i=0;i<8;i++)
                #pragma unroll
                for (int j=0;j<8;j++)
                    acc[i][j] = fmaf(a[i], b[j], acc[i][j]);
        }
        __syncthreads();
    }
    #pragma unroll
    for (int i=0;i<8;i++){
        int row = row0 + ty*8 + i;
        float na = mode ? nA[row] : 0.f;
        #pragma unroll
        for (int j=0;j<8;j++){
            int col = col0 + tx*8 + j;
            float v = acc[i][j];
            if (mode) v = (nB[col] + na) - 2.0f*v;
            C[(size_t)row*Nc + col] = v;
        }
    }
}

/* first-occurrence argmin per row (jnp.argmin semantics) */
__global__ void k_argmin(const float* __restrict__ dist, int* __restrict__ idx){
    int s = blockIdx.y, b = blockIdx.x, t = threadIdx.x;
    const float* row = dist + ((size_t)s*NB + b)*NM;
    float best = INFINITY; int bi = 0;
    for (int m=t; m<NM; m+=256){
        float v = row[m];
        if (v < best){ best = v; bi = m; }
    }
    __shared__ float sv[256]; __shared__ int si[256];
    sv[t]=best; si[t]=bi;
    __syncthreads();
    for (int o=128;o>0;o>>=1){
        if (t<o){
            if (sv[t+o] < sv[t] || (sv[t+o]==sv[t] && si[t+o] < si[t])){
                sv[t]=sv[t+o]; si[t]=si[t+o];
            }
        }
        __syncthreads();
    }
    if (t==0) idx[s*NB + b] = si[0];
}

__global__ void k_zero(float* __restrict__ p, int n){
    int i = blockIdx.x*blockDim.x + threadIdx.x;
    if (i<n) p[i]=0.f;
}

__global__ void k_hist(const int* __restrict__ idx, float* __restrict__ cnt){
    int s = blockIdx.y;
    int b = blockIdx.x*blockDim.x + threadIdx.x;
    atomicAdd(cnt + s*NM + idx[s*NB + b], 1.0f);
}

__global__ void k_perp(const float* __restrict__ cnt, float* __restrict__ out_perp, int stage){
    int s = blockIdx.x, t = threadIdx.x;
    float acc = 0.f;
    for (int m=t;m<NM;m+=256){
        float avg = cnt[s*NM+m] * (1.0f/(float)NB);
        acc += avg * logf(avg + 1e-10f);
    }
    acc = blockAllReduceSum(acc);
    if (t==0) out_perp[stage*2 + s] = expf(-acc);
}

__global__ void k_update(const float* __restrict__ E, const int* __restrict__ idx,
                         float* __restrict__ res, float* __restrict__ q,
                         float* __restrict__ out_sem, int stage){
    int s = blockIdx.y, b = blockIdx.x, t = threadIdx.x;
    int id = idx[s*NB + b];
    float e = E[(size_t)id*ND + t];
    size_t o = (size_t)s*NBD + (size_t)b*ND + t;
    res[o] -= e;
    q[o]   += e;
    if (t==0) out_sem[(size_t)s*NB*NK + (size_t)b*NK + stage] = (float)id;
}

/* cmcm softmax over rows; writes concatenated/crossed ph & log(ph+1e-10) */
__global__ void k_softmax(const float* __restrict__ dist,
                          float* __restrict__ X, float* __restrict__ Y){
    int s = blockIdx.y, b = blockIdx.x, t = threadIdx.x;
    const float* row = dist + ((size_t)s*NB + b)*NM;
    float z[32];
    float mx = -INFINITY;
    #pragma unroll
    for (int i=0;i<32;i++){
        float v = row[i*256 + t];
        v = -sqrtf(fmaxf(v, 0.f));
        z[i] = v;
        mx = fmaxf(mx, v);
    }
    mx = blockAllReduceMax(mx);
    float sm = 0.f;
    #pragma unroll
    for (int i=0;i<32;i++){
        float e = expf(z[i]-mx);
        z[i] = e; sm += e;
    }
    sm = blockAllReduceSum(sm);
    float* xr = X + (size_t)b*(2*NM) + (size_t)s*NM;     /* ph_pcf | ph_plm   */
    float* yr = Y + (size_t)b*(2*NM) + (size_t)(1-s)*NM; /* lp_plm | lp_pcf   */
    #pragma unroll
    for (int i=0;i<32;i++){
        int m = i*256 + t;
        float ph = z[i]/sm;
        xr[m] = ph;
        yr[m] = logf(ph + 1e-10f);
    }
}

__global__ void k_minred(const float* __restrict__ S, unsigned* mo){
    size_t NN = (size_t)NB*NB;
    float best = INFINITY;
    for (size_t n = (size_t)blockIdx.x*blockDim.x + threadIdx.x; n < NN;
         n += (size_t)gridDim.x*blockDim.x)
        best = fminf(best, S[n]);
    __shared__ float sh[256];
    sh[threadIdx.x]=best; __syncthreads();
    for (int o=128;o>0;o>>=1){
        if (threadIdx.x<o) sh[threadIdx.x]=fminf(sh[threadIdx.x],sh[threadIdx.x+o]);
        __syncthreads();
    }
    if (threadIdx.x==0) atomicMin(mo, f2ord(sh[0]));
}

__global__ void k_ratio(const float* __restrict__ S, const unsigned* mo, float* lr){
    int i = blockIdx.x, t = threadIdx.x;
    float Max = -ord2f(*mo);
    const float* row = S + (size_t)i*NB;
    float sm = 0.f;
    for (int j=t;j<NB;j+=256) sm += expf(row[j] + Max);
    sm = blockAllReduceSum(sm);
    if (t==0){
        float diag = expf(row[i] + Max);
        float ratio = diag / (sm + 1e-5f);
        atomicAdd(lr, logf(ratio));
    }
}

__global__ void k_msequant(const float* __restrict__ pcf, const float* __restrict__ plm,
                           const float* __restrict__ q, float* __restrict__ out,
                           float* mse){
    int n = blockIdx.x*blockDim.x + threadIdx.x;
    float p  = pcf[n], pl = plm[n];
    float qp = q[n],   ql = q[NBD + n];
    float qzp = p  + (qp - p);   /* straight-through: fl(p + fl(q-p)) */
    float qzl = pl + (ql - pl);
    out[n]        = qzp;
    out[NBD + n]  = qzl;
    float d0 = p - qzp, d1 = p - qzl, d2 = pl - qzl, d3 = pl - qzp;
    float s0 = blockAllReduceSum(d0*d0);
    float s1 = blockAllReduceSum(d1*d1);
    float s2 = blockAllReduceSum(d2*d2);
    float s3 = blockAllReduceSum(d3*d3);
    if (threadIdx.x==0){
        atomicAdd(mse+0, s0); atomicAdd(mse+1, s1);
        atomicAdd(mse+2, s2); atomicAdd(mse+3, s3);
    }
}

__global__ void k_final(const float* lr, const float* mse, float* out_loss){
    float Lc = -(*lr) / (float)NB;
    float inv = 1.0f/(float)NBD;
    float pcf_loss = 0.25f*2.0f*(mse[0]*inv) + 0.25f*(mse[1]*inv);
    float plm_loss = 0.25f*2.0f*(mse[2]*inv) + 0.25f*(mse[3]*inv);
    *out_loss = 0.5f*Lc + pcf_loss + plm_loss;
}

/* ------------------------------------------------------------------ */
extern "C" void kernel_launch(void* const* d_in, const int* in_sizes, int n_in,
                              void* d_out, int out_size){
    const float* pcf = (const float*)d_in[0];
    const float* plm = (const float*)d_in[1];
    const float* emb = (const float*)d_in[2];
    float* out = (float*)d_out;

    void *p;
    float *res,*q,*normX,*normE,*dist,*X,*Y,*S,*cnt,*lr,*mse;
    int* idx; unsigned* mo;
    cudaGetSymbolAddress(&p, g_res);   res  = (float*)p;
    cudaGetSymbolAddress(&p, g_q);     q    = (float*)p;
    cudaGetSymbolAddress(&p, g_normX); normX= (float*)p;
    cudaGetSymbolAddress(&p, g_normE); normE= (float*)p;
    cudaGetSymbolAddress(&p, g_dist);  dist = (float*)p;
    cudaGetSymbolAddress(&p, g_X);     X    = (float*)p;
    cudaGetSymbolAddress(&p, g_Y);     Y    = (float*)p;
    cudaGetSymbolAddress(&p, g_S);     S    = (float*)p;
    cudaGetSymbolAddress(&p, g_idx);   idx  = (int*)p;
    cudaGetSymbolAddress(&p, g_cnt);   cnt  = (float*)p;
    cudaGetSymbolAddress(&p, g_minord);mo   = (unsigned*)p;
    cudaGetSymbolAddress(&p, g_lr);    lr   = (float*)p;
    cudaGetSymbolAddress(&p, g_mse);   mse  = (float*)p;

    /* output layout: quantized [2,B,D] | loss | sem_ids [2,B,K] | perp [K,2] */
    float* out_loss = out + (size_t)2*NBD;
    float* out_sem  = out_loss + 1;
    float* out_perp = out_sem + (size_t)2*NB*NK;

    k_init<<<(2*NBD+255)/256, 256>>>(pcf, plm, res, q, mo, lr, mse);
    k_rownorm<<<NK*NM, 128>>>(emb, normE);

    /* cmcm: only the LAST stage's Lcmcm survives; uses ORIGINAL inputs + E3 */
    const float* E3 = emb + (size_t)3*NM*ND;
    k_rownorm<<<NB,128>>>(pcf, normX);
    k_rownorm<<<NB,128>>>(plm, normX+NB);
    k_gemm<<<dim3(NM/128, NB/128), 256>>>(pcf, E3, dist,                 NB, NM, ND, normX,    normE+3*NM, 1);
    k_gemm<<<dim3(NM/128, NB/128), 256>>>(plm, E3, dist+(size_t)NB*NM,   NB, NM, ND, normX+NB, normE+3*NM, 1);
    k_softmax<<<dim3(NB,2), 256>>>(dist, X, Y);
    k_gemm<<<dim3(NB/128, NB/128), 256>>>(X, Y, S, NB, NB, 2*NM, (const float*)0, (const float*)0, 0);

    /* residual VQ stages */
    for (int st=0; st<NK; ++st){
        const float* E = emb + (size_t)st*NM*ND;
        k_rownorm<<<NB,128>>>(res,      normX);
        k_rownorm<<<NB,128>>>(res+NBD,  normX+NB);
        k_gemm<<<dim3(NM/128, NB/128), 256>>>(res,     E, dist,               NB, NM, ND, normX,    normE+st*NM, 1);
        k_gemm<<<dim3(NM/128, NB/128), 256>>>(res+NBD, E, dist+(size_t)NB*NM, NB, NM, ND, normX+NB, normE+st*NM, 1);
        k_argmin<<<dim3(NB,2),256>>>(dist, idx);
        k_zero<<<(2*NM+255)/256,256>>>(cnt, 2*NM);
        k_hist<<<dim3(NB/256,2),256>>>(idx, cnt);
        k_perp<<<2,256>>>(cnt, out_perp, st);
        k_update<<<dim3(NB,2),128>>>(E, idx, res, q, out_sem, st);
    }

    /* cmcm loss reductions */
    k_minred<<<4096,256>>>(S, mo);
    k_ratio<<<NB,256>>>(S, mo, lr);
    k_msequant<<<NBD/256,256>>>(pcf, plm, q, out, mse);
    k_final<<<1,1>>>(lr, mse, out_loss);
}

// round 7
// speedup vs baseline: 3.1545x; 3.1545x over previous
#include <cuda_runtime.h>
#include <cuda_bf16.h>
#include <math.h>
#include <stdint.h>

#define NB 4096
#define ND 128
#define NM 8192
#define NK 4
#define NBD (NB*ND)   /* 524288 */

/* ------------------------------------------------------------------ */
/* device scratch (static: allocation rules forbid cudaMalloc)         */
/* ------------------------------------------------------------------ */
__device__ float g_res[2*NBD];             /* residuals pcf/plm          */
__device__ float g_q[2*NBD];               /* quantized accumulators     */
__device__ float g_normX[2*NB];
__device__ float g_normE[NK*NM];
__device__ float g_dist[2*NB*NM];          /* 256 MB: cmcm dists only    */
__device__ __nv_bfloat16 g_Xb[(size_t)NB*2*NM];  /* 128 MB ph concat     */
__device__ __nv_bfloat16 g_Yb[(size_t)NB*2*NM];  /* 128 MB logph concat  */
__device__ float g_S[(size_t)NB*NB];       /* 64 MB Scode                */
__device__ unsigned long long g_amin[2*NB];/* packed (ord(dist),idx)     */
__device__ float g_cnt[2*NM];
__device__ unsigned g_minord;
__device__ float g_lr;
__device__ float g_mse[4];

/* ------------------------------------------------------------------ */
/* helpers                                                             */
/* ------------------------------------------------------------------ */
__device__ __forceinline__ float blockAllReduceSum(float v){
    __shared__ float sh[33];
    int lane = threadIdx.x & 31, w = threadIdx.x >> 5;
    __syncthreads();
    #pragma unroll
    for (int o=16;o>0;o>>=1) v += __shfl_down_sync(0xffffffffu, v, o);
    if (lane==0) sh[w] = v;
    __syncthreads();
    if (threadIdx.x==0){
        float s = 0.f; int nw = blockDim.x >> 5;
        for (int i=0;i<nw;i++) s += sh[i];
        sh[32] = s;
    }
    __syncthreads();
    return sh[32];
}
__device__ __forceinline__ float blockAllReduceMax(float v){
    __shared__ float sh[33];
    int lane = threadIdx.x & 31, w = threadIdx.x >> 5;
    __syncthreads();
    #pragma unroll
    for (int o=16;o>0;o>>=1) v = fmaxf(v, __shfl_down_sync(0xffffffffu, v, o));
    if (lane==0) sh[w] = v;
    __syncthreads();
    if (threadIdx.x==0){
        float s = -INFINITY; int nw = blockDim.x >> 5;
        for (int i=0;i<nw;i++) s = fmaxf(s, sh[i]);
        sh[32] = s;
    }
    __syncthreads();
    return sh[32];
}
__device__ __forceinline__ unsigned f2ord(float f){
    unsigned u = __float_as_uint(f);
    return (u >> 31) ? ~u : (u | 0x80000000u);
}
__device__ __forceinline__ float ord2f(unsigned o){
    unsigned u = (o >> 31) ? (o ^ 0x80000000u) : ~o;
    return __uint_as_float(u);
}
__device__ __forceinline__ void cp16(void* dst, const void* src){
    unsigned ds = (unsigned)__cvta_generic_to_shared(dst);
    asm volatile("cp.async.cg.shared.global [%0], [%1], 16;\n" :: "r"(ds), "l"(src));
}
__device__ __forceinline__ void ldm4(unsigned &r0,unsigned&r1,unsigned&r2,unsigned&r3,
                                     const void* p){
    unsigned a = (unsigned)__cvta_generic_to_shared(p);
    asm volatile("ldmatrix.sync.aligned.m8n8.x4.shared.b16 {%0,%1,%2,%3}, [%4];\n"
        : "=r"(r0),"=r"(r1),"=r"(r2),"=r"(r3) : "r"(a));
}
__device__ __forceinline__ void mma_bf16(float* d, const unsigned* a, const unsigned* b){
    asm volatile("mma.sync.aligned.m16n8k16.row.col.f32.bf16.bf16.f32 "
        "{%0,%1,%2,%3}, {%4,%5,%6,%7}, {%8,%9}, {%0,%1,%2,%3};\n"
        : "+f"(d[0]),"+f"(d[1]),"+f"(d[2]),"+f"(d[3])
        : "r"(a[0]),"r"(a[1]),"r"(a[2]),"r"(a[3]), "r"(b[0]),"r"(b[1]));
}

/* ------------------------------------------------------------------ */
/* kernels                                                             */
/* ------------------------------------------------------------------ */
__global__ void k_init(const float* __restrict__ pcf, const float* __restrict__ plm,
                       float* __restrict__ res, float* __restrict__ q,
                       unsigned* minord, float* lr, float* mse){
    int n = blockIdx.x*blockDim.x + threadIdx.x;
    if (n < 2*NBD){
        res[n] = (n < NBD) ? pcf[n] : plm[n - NBD];
        q[n] = 0.f;
    }
    if (n == 0){
        *minord = 0xFFFFFFFFu; *lr = 0.f;
        mse[0]=0.f; mse[1]=0.f; mse[2]=0.f; mse[3]=0.f;
    }
}

__global__ void k_rownorm(const float* __restrict__ x, float* __restrict__ out){
    int r = blockIdx.x;
    float v = x[(size_t)r*ND + threadIdx.x];
    float s = blockAllReduceSum(v*v);
    if (threadIdx.x==0) out[r] = s;
}

/* NT fp32 SGEMM, 128x128 tile, K-chunk 16.
   mode=1: write dist = (nB[col]+nA[row]) - 2*acc into C
   mode=2: fused per-row argmin -> atomicMin into amin (no C write) */
__global__ void __launch_bounds__(256, 2) k_gemm(
    const float* __restrict__ A, const float* __restrict__ Bm, float* __restrict__ C,
    int Nc, int Kd,
    const float* __restrict__ nA, const float* __restrict__ nB,
    unsigned long long* __restrict__ amin, int mode)
{
    __shared__ float As[16][128];
    __shared__ float Bs[16][128];
    int t = threadIdx.x;
    int tx = t & 15, ty = t >> 4;
    int row0 = blockIdx.y * 128;
    int col0 = blockIdx.x * 128;
    float acc[8][8];
    #pragma unroll
    for (int i=0;i<8;i++)
        #pragma unroll
        for (int j=0;j<8;j++) acc[i][j] = 0.f;

    for (int k0=0; k0<Kd; k0+=16){
        #pragma unroll
        for (int u=0;u<2;u++){
            int l = t*2+u;
            int r = l >> 2;
            int c = (l & 3) << 2;
            float4 va = *(const float4*)(A  + (size_t)(row0 + r)*Kd + k0 + c);
            As[c+0][r]=va.x; As[c+1][r]=va.y; As[c+2][r]=va.z; As[c+3][r]=va.w;
            float4 vb = *(const float4*)(Bm + (size_t)(col0 + r)*Kd + k0 + c);
            Bs[c+0][r]=vb.x; Bs[c+1][r]=vb.y; Bs[c+2][r]=vb.z; Bs[c+3][r]=vb.w;
        }
        __syncthreads();
        #pragma unroll
        for (int kk=0;kk<16;kk++){
            float a[8], b[8];
            #pragma unroll
            for (int i=0;i<8;i++) a[i] = As[kk][ty*8+i];
            #pragma unroll
            for (int j=0;j<8;j++) b[j] = Bs[kk][tx*8+j];
            #pragma unroll
            for (int i=0;i<8;i++)
                #pragma unroll
                for (int j=0;j<8;j++)
                    acc[i][j] = fmaf(a[i], b[j], acc[i][j]);
        }
        __syncthreads();
    }

    if (mode == 2){
        /* per-row argmin over this block's 128 cols, then atomicMin */
        #pragma unroll
        for (int i=0;i<8;i++){
            int row = row0 + ty*8 + i;
            float na = nA[row];
            float best = INFINITY; int bc = 0;
            #pragma unroll
            for (int j=0;j<8;j++){
                int col = col0 + tx*8 + j;
                float v = (nB[col] + na) - 2.0f*acc[i][j];
                if (v < best){ best = v; bc = col; }
            }
            unsigned long long p =
                ((unsigned long long)f2ord(best) << 32) | (unsigned)bc;
            #pragma unroll
            for (int o=8;o>0;o>>=1){
                unsigned long long qv = __shfl_down_sync(0xffffffffu, p, o, 16);
                if (qv < p) p = qv;
            }
            if (tx==0) atomicMin(amin + row, p);
        }
    } else {
        #pragma unroll
        for (int i=0;i<8;i++){
            int row = row0 + ty*8 + i;
            float na = nA[row];
            #pragma unroll
            for (int j=0;j<8;j++){
                int col = col0 + tx*8 + j;
                float v = (nB[col] + na) - 2.0f*acc[i][j];
                C[(size_t)row*Nc + col] = v;
            }
        }
    }
}

/* bf16 tensor-core NT GEMM: C[i,j] = sum_k A[i,k]*B[j,k], fp32 accum.
   128x128 tile, BK=32, 8 warps (4 M x 2 N), warp tile 32x64, cp.async 2-stage. */
__global__ void __launch_bounds__(256,1) k_scode(
    const __nv_bfloat16* __restrict__ A, const __nv_bfloat16* __restrict__ B,
    float* __restrict__ C, int Kd, int Nc)
{
    __shared__ __nv_bfloat16 As[2][128*32];
    __shared__ __nv_bfloat16 Bs[2][128*32];
    const int t = threadIdx.x;
    const int lane = t & 31, warp = t >> 5;
    const int wm = warp & 3, wn = warp >> 2;
    const int row0 = blockIdx.y*128, col0 = blockIdx.x*128;

    float acc[2][8][4];
    #pragma unroll
    for (int i=0;i<2;i++)
        #pragma unroll
        for (int n=0;n<8;n++)
            #pragma unroll
            for (int x=0;x<4;x++) acc[i][n][x] = 0.f;

    auto prefetch = [&](int kb, int buf){
        size_t k0 = (size_t)kb*32;
        int r1 = t>>2, c1 = t&3;
        int s1 = c1 ^ ((r1>>1)&3);
        cp16(&As[buf][r1*32 + s1*8], A + (size_t)(row0+r1)*Kd + k0 + c1*8);
        cp16(&Bs[buf][r1*32 + s1*8], B + (size_t)(col0+r1)*Kd + k0 + c1*8);
        int r2 = 64 + r1;
        int s2 = c1 ^ ((r2>>1)&3);
        cp16(&As[buf][r2*32 + s2*8], A + (size_t)(row0+r2)*Kd + k0 + c1*8);
        cp16(&Bs[buf][r2*32 + s2*8], B + (size_t)(col0+r2)*Kd + k0 + c1*8);
    };

    const int nKb = Kd/32;
    prefetch(0, 0);
    asm volatile("cp.async.commit_group;\n" ::);

    for (int kb=0; kb<nKb; ++kb){
        int buf = kb & 1;
        asm volatile("cp.async.wait_group 0;\n" ::);
        __syncthreads();
        if (kb+1 < nKb){
            prefetch(kb+1, buf^1);
            asm volatile("cp.async.commit_group;\n" ::);
        }
        #pragma unroll
        for (int ks=0; ks<2; ++ks){
            unsigned a[2][4];
            #pragma unroll
            for (int i=0;i<2;i++){
                int r  = wm*32 + i*16 + (lane & 15);
                int cb = ks*2 + (lane >> 4);
                ldm4(a[i][0],a[i][1],a[i][2],a[i][3],
                     &As[buf][r*32 + ((cb ^ ((r>>1)&3))<<3)]);
            }
            unsigned b[8][2];
            #pragma unroll
            for (int j=0;j<4;j++){
                int g  = lane >> 3;
                int r  = wn*64 + j*16 + (lane & 7) + ((g>>1)<<3);
                int cb = ks*2 + (g & 1);
                unsigned b0,b1,b2,b3;
                ldm4(b0,b1,b2,b3, &Bs[buf][r*32 + ((cb ^ ((r>>1)&3))<<3)]);
                b[2*j][0]=b0; b[2*j][1]=b1; b[2*j+1][0]=b2; b[2*j+1][1]=b3;
            }
            #pragma unroll
            for (int i=0;i<2;i++)
                #pragma unroll
                for (int n=0;n<8;n++)
                    mma_bf16(acc[i][n], a[i], b[n]);
        }
    }

    #pragma unroll
    for (int i=0;i<2;i++){
        int r = row0 + wm*32 + i*16 + (lane>>2);
        #pragma unroll
        for (int n=0;n<8;n++){
            int c = col0 + wn*64 + n*8 + (lane&3)*2;
            *(float2*)(C + (size_t)r*Nc + c)     = make_float2(acc[i][n][0], acc[i][n][1]);
            *(float2*)(C + (size_t)(r+8)*Nc + c) = make_float2(acc[i][n][2], acc[i][n][3]);
        }
    }
}

__global__ void k_initamin(unsigned long long* a){
    int i = blockIdx.x*blockDim.x + threadIdx.x;
    if (i < 2*NB) a[i] = 0xFFFFFFFFFFFFFFFFull;
}

__global__ void k_zero(float* __restrict__ p, int n){
    int i = blockIdx.x*blockDim.x + threadIdx.x;
    if (i<n) p[i]=0.f;
}

__global__ void k_hist(const unsigned long long* __restrict__ amin, float* __restrict__ cnt){
    int s = blockIdx.y;
    int b = blockIdx.x*blockDim.x + threadIdx.x;
    int id = (int)(unsigned)(amin[s*NB + b] & 0xFFFFFFFFull);
    atomicAdd(cnt + s*NM + id, 1.0f);
}

__global__ void k_perp(const float* __restrict__ cnt, float* __restrict__ out_perp, int stage){
    int s = blockIdx.x, t = threadIdx.x;
    float acc = 0.f;
    for (int m=t;m<NM;m+=256){
        float avg = cnt[s*NM+m] * (1.0f/(float)NB);
        acc += avg * logf(avg + 1e-10f);
    }
    acc = blockAllReduceSum(acc);
    if (t==0) out_perp[stage*2 + s] = expf(-acc);
}

__global__ void k_update(const float* __restrict__ E, const unsigned long long* __restrict__ amin,
                         float* __restrict__ res, float* __restrict__ q,
                         float* __restrict__ out_sem, int stage){
    int s = blockIdx.y, b = blockIdx.x, t = threadIdx.x;
    int id = (int)(unsigned)(amin[s*NB + b] & 0xFFFFFFFFull);
    float e = E[(size_t)id*ND + t];
    size_t o = (size_t)s*NBD + (size_t)b*ND + t;
    res[o] -= e;
    q[o]   += e;
    if (t==0) out_sem[(size_t)s*NB*NK + (size_t)b*NK + stage] = (float)id;
}

/* cmcm softmax; writes bf16 concatenated/crossed ph and log(ph+1e-10) */
__global__ void k_softmax(const float* __restrict__ dist,
                          __nv_bfloat16* __restrict__ X, __nv_bfloat16* __restrict__ Y){
    int s = blockIdx.y, b = blockIdx.x, t = threadIdx.x;
    const float* row = dist + ((size_t)s*NB + b)*NM;
    float z[32];
    float mx = -INFINITY;
    #pragma unroll
    for (int i=0;i<32;i++){
        float v = row[i*256 + t];
        v = -sqrtf(fmaxf(v, 0.f));
        z[i] = v;
        mx = fmaxf(mx, v);
    }
    mx = blockAllReduceMax(mx);
    float sm = 0.f;
    #pragma unroll
    for (int i=0;i<32;i++){
        float e = expf(z[i]-mx);
        z[i] = e; sm += e;
    }
    sm = blockAllReduceSum(sm);
    __nv_bfloat16* xr = X + (size_t)b*(2*NM) + (size_t)s*NM;
    __nv_bfloat16* yr = Y + (size_t)b*(2*NM) + (size_t)(1-s)*NM;
    #pragma unroll
    for (int i=0;i<32;i++){
        int m = i*256 + t;
        float ph = z[i]/sm;
        xr[m] = __float2bfloat16(ph);
        yr[m] = __float2bfloat16(logf(ph + 1e-10f));
    }
}

__global__ void k_minred(const float* __restrict__ S, unsigned* mo){
    size_t NN = (size_t)NB*NB;
    float best = INFINITY;
    for (size_t n = (size_t)blockIdx.x*blockDim.x + threadIdx.x; n < NN;
         n += (size_t)gridDim.x*blockDim.x)
        best = fminf(best, S[n]);
    __shared__ float sh[256];
    sh[threadIdx.x]=best; __syncthreads();
    for (int o=128;o>0;o>>=1){
        if (threadIdx.x<o) sh[threadIdx.x]=fminf(sh[threadIdx.x],sh[threadIdx.x+o]);
        __syncthreads();
    }
    if (threadIdx.x==0) atomicMin(mo, f2ord(sh[0]));
}

__global__ void k_ratio(const float* __restrict__ S, const unsigned* mo, float* lr){
    int i = blockIdx.x, t = threadIdx.x;
    float Max = -ord2f(*mo);
    const float* row = S + (size_t)i*NB;
    float sm = 0.f;
    for (int j=t;j<NB;j+=256) sm += expf(row[j] + Max);
    sm = blockAllReduceSum(sm);
    if (t==0){
        float diag = expf(row[i] + Max);
        float ratio = diag / (sm + 1e-5f);
        atomicAdd(lr, logf(ratio));
    }
}

__global__ void k_msequant(const float* __restrict__ pcf, const float* __restrict__ plm,
                           const float* __restrict__ q, float* __restrict__ out,
                           float* mse){
    int n = blockIdx.x*blockDim.x + threadIdx.x;
    float p  = pcf[n], pl = plm[n];
    float qp = q[n],   ql = q[NBD + n];
    float qzp = p  + (qp - p);
    float qzl = pl + (ql - pl);
    out[n]        = qzp;
    out[NBD + n]  = qzl;
    float d0 = p - qzp, d1 = p - qzl, d2 = pl - qzl, d3 = pl - qzp;
    float s0 = blockAllReduceSum(d0*d0);
    float s1 = blockAllReduceSum(d1*d1);
    float s2 = blockAllReduceSum(d2*d2);
    float s3 = blockAllReduceSum(d3*d3);
    if (threadIdx.x==0){
        atomicAdd(mse+0, s0); atomicAdd(mse+1, s1);
        atomicAdd(mse+2, s2); atomicAdd(mse+3, s3);
    }
}

__global__ void k_final(const float* lr, const float* mse, float* out_loss){
    float Lc = -(*lr) / (float)NB;
    float inv = 1.0f/(float)NBD;
    float pcf_loss = 0.25f*2.0f*(mse[0]*inv) + 0.25f*(mse[1]*inv);
    float plm_loss = 0.25f*2.0f*(mse[2]*inv) + 0.25f*(mse[3]*inv);
    *out_loss = 0.5f*Lc + pcf_loss + plm_loss;
}

/* ------------------------------------------------------------------ */
extern "C" void kernel_launch(void* const* d_in, const int* in_sizes, int n_in,
                              void* d_out, int out_size){
    const float* pcf = (const float*)d_in[0];
    const float* plm = (const float*)d_in[1];
    const float* emb = (const float*)d_in[2];
    float* out = (float*)d_out;

    void *p;
    float *res,*q,*normX,*normE,*dist,*S,*cnt,*lr,*mse;
    __nv_bfloat16 *Xb,*Yb;
    unsigned long long* amin;
    unsigned* mo;
    cudaGetSymbolAddress(&p, g_res);   res  = (float*)p;
    cudaGetSymbolAddress(&p, g_q);     q    = (float*)p;
    cudaGetSymbolAddress(&p, g_normX); normX= (float*)p;
    cudaGetSymbolAddress(&p, g_normE); normE= (float*)p;
    cudaGetSymbolAddress(&p, g_dist);  dist = (float*)p;
    cudaGetSymbolAddress(&p, g_Xb);    Xb   = (__nv_bfloat16*)p;
    cudaGetSymbolAddress(&p, g_Yb);    Yb   = (__nv_bfloat16*)p;
    cudaGetSymbolAddress(&p, g_S);     S    = (float*)p;
    cudaGetSymbolAddress(&p, g_amin);  amin = (unsigned long long*)p;
    cudaGetSymbolAddress(&p, g_cnt);   cnt  = (float*)p;
    cudaGetSymbolAddress(&p, g_minord);mo   = (unsigned*)p;
    cudaGetSymbolAddress(&p, g_lr);    lr   = (float*)p;
    cudaGetSymbolAddress(&p, g_mse);   mse  = (float*)p;

    /* output layout: quantized [2,B,D] | loss | sem_ids [2,B,K] | perp [K,2] */
    float* out_loss = out + (size_t)2*NBD;
    float* out_sem  = out_loss + 1;
    float* out_perp = out_sem + (size_t)2*NB*NK;

    k_init<<<(2*NBD+255)/256, 256>>>(pcf, plm, res, q, mo, lr, mse);
    k_rownorm<<<NK*NM, 128>>>(emb, normE);

    /* cmcm: only last stage's Lcmcm survives; uses ORIGINAL inputs + E3 */
    const float* E3 = emb + (size_t)3*NM*ND;
    k_rownorm<<<NB,128>>>(pcf, normX);
    k_rownorm<<<NB,128>>>(plm, normX+NB);
    k_gemm<<<dim3(NM/128, NB/128), 256>>>(pcf, E3, dist,               NM, ND, normX,    normE+3*NM, (unsigned long long*)0, 1);
    k_gemm<<<dim3(NM/128, NB/128), 256>>>(plm, E3, dist+(size_t)NB*NM, NM, ND, normX+NB, normE+3*NM, (unsigned long long*)0, 1);
    k_softmax<<<dim3(NB,2), 256>>>(dist, Xb, Yb);
    k_scode<<<dim3(NB/128, NB/128), 256>>>(Xb, Yb, S, 2*NM, NB);

    /* residual VQ stages: dist GEMM with fused argmin (no dist materialization) */
    for (int st=0; st<NK; ++st){
        const float* E = emb + (size_t)st*NM*ND;
        k_initamin<<<(2*NB+255)/256, 256>>>(amin);
        k_rownorm<<<NB,128>>>(res,      normX);
        k_rownorm<<<NB,128>>>(res+NBD,  normX+NB);
        k_gemm<<<dim3(NM/128, NB/128), 256>>>(res,     E, (float*)0, NM, ND, normX,    normE+st*NM, amin,      2);
        k_gemm<<<dim3(NM/128, NB/128), 256>>>(res+NBD, E, (float*)0, NM, ND, normX+NB, normE+st*NM, amin+NB,   2);
        k_zero<<<(2*NM+255)/256,256>>>(cnt, 2*NM);
        k_hist<<<dim3(NB/256,2),256>>>(amin, cnt);
        k_perp<<<2,256>>>(cnt, out_perp, st);
        k_update<<<dim3(NB,2),128>>>(E, amin, res, q, out_sem, st);
    }

    /* cmcm loss reductions */
    k_minred<<<4096,256>>>(S, mo);
    k_ratio<<<NB,256>>>(S, mo, lr);
    k_msequant<<<NBD/256,256>>>(pcf, plm, q, out, mse);
    k_final<<<1,1>>>(lr, mse, out_loss);
}

// round 11
// speedup vs baseline: 4.9881x; 1.5812x over previous
#include <cuda_runtime.h>
#include <cuda_bf16.h>
#include <math.h>
#include <stdint.h>

#define NB 4096
#define ND 128
#define NM 8192
#define NK 4
#define NBD (NB*ND)   /* 524288 */
#define KS6 768       /* 6 product-term blocks x 128, small->large order */

/* ------------------------------------------------------------------ */
/* device scratch (static: allocation rules forbid cudaMalloc)         */
/* ------------------------------------------------------------------ */
__device__ float g_res[2*NBD];             /* residuals pcf/plm          */
__device__ float g_q[2*NBD];               /* quantized accumulators     */
__device__ float g_normX[2*NB];
__device__ float g_normE[NK*NM];
__device__ float g_dist[2*NB*NM];          /* 256 MB: cmcm dists only    */
__device__ __nv_bfloat16 g_Eb[(size_t)NK*NM*KS6];  /* 50 MB split E (B-layout) */
__device__ __nv_bfloat16 g_Xp[(size_t)2*NB*KS6];   /* 12.6 MB split res (A-layout) */
__device__ __nv_bfloat16 g_Xb[(size_t)NB*2*NM];  /* 128 MB ph concat     */
__device__ __nv_bfloat16 g_Yb[(size_t)NB*2*NM];  /* 128 MB logph concat  */
__device__ float g_S[(size_t)NB*NB];       /* 64 MB Scode                */
__device__ unsigned long long g_amin[2*NB];/* packed (ord(dist),idx)     */
__device__ float g_cnt[2*NM];
__device__ unsigned g_minord;
__device__ float g_lr;
__device__ float g_mse[4];

/* ------------------------------------------------------------------ */
/* helpers                                                             */
/* ------------------------------------------------------------------ */
__device__ __forceinline__ float blockAllReduceSum(float v){
    __shared__ float sh[33];
    int lane = threadIdx.x & 31, w = threadIdx.x >> 5;
    __syncthreads();
    #pragma unroll
    for (int o=16;o>0;o>>=1) v += __shfl_down_sync(0xffffffffu, v, o);
    if (lane==0) sh[w] = v;
    __syncthreads();
    if (threadIdx.x==0){
        float s = 0.f; int nw = blockDim.x >> 5;
        for (int i=0;i<nw;i++) s += sh[i];
        sh[32] = s;
    }
    __syncthreads();
    return sh[32];
}
__device__ __forceinline__ float blockAllReduceMax(float v){
    __shared__ float sh[33];
    int lane = threadIdx.x & 31, w = threadIdx.x >> 5;
    __syncthreads();
    #pragma unroll
    for (int o=16;o>0;o>>=1) v = fmaxf(v, __shfl_down_sync(0xffffffffu, v, o));
    if (lane==0) sh[w] = v;
    __syncthreads();
    if (threadIdx.x==0){
        float s = -INFINITY; int nw = blockDim.x >> 5;
        for (int i=0;i<nw;i++) s = fmaxf(s, sh[i]);
        sh[32] = s;
    }
    __syncthreads();
    return sh[32];
}
__device__ __forceinline__ unsigned f2ord(float f){
    unsigned u = __float_as_uint(f);
    return (u >> 31) ? ~u : (u | 0x80000000u);
}
__device__ __forceinline__ float ord2f(unsigned o){
    unsigned u = (o >> 31) ? (o ^ 0x80000000u) : ~o;
    return __uint_as_float(u);
}
__device__ __forceinline__ void cp16(void* dst, const void* src){
    unsigned ds = (unsigned)__cvta_generic_to_shared(dst);
    asm volatile("cp.async.cg.shared.global [%0], [%1], 16;\n" :: "r"(ds), "l"(src));
}
__device__ __forceinline__ void ldm4(unsigned &r0,unsigned&r1,unsigned&r2,unsigned&r3,
                                     const void* p){
    unsigned a = (unsigned)__cvta_generic_to_shared(p);
    asm volatile("ldmatrix.sync.aligned.m8n8.x4.shared.b16 {%0,%1,%2,%3}, [%4];\n"
        : "=r"(r0),"=r"(r1),"=r"(r2),"=r"(r3) : "r"(a));
}
__device__ __forceinline__ void mma_bf16(float* d, const unsigned* a, const unsigned* b){
    asm volatile("mma.sync.aligned.m16n8k16.row.col.f32.bf16.bf16.f32 "
        "{%0,%1,%2,%3}, {%4,%5,%6,%7}, {%8,%9}, {%0,%1,%2,%3};\n"
        : "+f"(d[0]),"+f"(d[1]),"+f"(d[2]),"+f"(d[3])
        : "r"(a[0]),"r"(a[1]),"r"(a[2]),"r"(a[3]), "r"(b[0]),"r"(b[1]));
}

/* ------------------------------------------------------------------ */
/* kernels                                                             */
/* ------------------------------------------------------------------ */
__global__ void k_init(const float* __restrict__ pcf, const float* __restrict__ plm,
                       float* __restrict__ res, float* __restrict__ q,
                       unsigned* minord, float* lr, float* mse){
    int n = blockIdx.x*blockDim.x + threadIdx.x;
    if (n < 2*NBD){
        res[n] = (n < NBD) ? pcf[n] : plm[n - NBD];
        q[n] = 0.f;
    }
    if (n == 0){
        *minord = 0xFFFFFFFFu; *lr = 0.f;
        mse[0]=0.f; mse[1]=0.f; mse[2]=0.f; mse[3]=0.f;
    }
}

__global__ void k_rownorm(const float* __restrict__ x, float* __restrict__ out){
    int r = blockIdx.x;
    float v = x[(size_t)r*ND + threadIdx.x];
    float s = blockAllReduceSum(v*v);
    if (threadIdx.x==0) out[r] = s;
}

/* 3-plane bf16 split, product-term concatenation, SMALL->LARGE order:
   A-layout (x side): [h, m, m, l, h, h]
   B-layout (e side): [m, h, m, h, l, h]
   => accumulation order hm+mh+mm+lh+hl+hh: the 640 small-term products
      round against a tiny partial sum; hh accumulates last like a plain
      fp32 dot. Total error ~ fp32-summation class (~5e-9). */
__global__ void k_splitA(const float* __restrict__ x, __nv_bfloat16* __restrict__ o){
    int r = blockIdx.x, t = threadIdx.x;
    float v = x[(size_t)r*ND + t];
    __nv_bfloat16 h = __float2bfloat16(v);
    float r1 = v - __bfloat162float(h);
    __nv_bfloat16 m = __float2bfloat16(r1);
    float r2 = r1 - __bfloat162float(m);
    __nv_bfloat16 l = __float2bfloat16(r2);
    size_t base = (size_t)r*KS6;
    o[base +   0 + t] = h;
    o[base + 128 + t] = m;
    o[base + 256 + t] = m;
    o[base + 384 + t] = l;
    o[base + 512 + t] = h;
    o[base + 640 + t] = h;
}
__global__ void k_splitB(const float* __restrict__ x, __nv_bfloat16* __restrict__ o){
    int r = blockIdx.x, t = threadIdx.x;
    float v = x[(size_t)r*ND + t];
    __nv_bfloat16 h = __float2bfloat16(v);
    float r1 = v - __bfloat162float(h);
    __nv_bfloat16 m = __float2bfloat16(r1);
    float r2 = r1 - __bfloat162float(m);
    __nv_bfloat16 l = __float2bfloat16(r2);
    size_t base = (size_t)r*KS6;
    o[base +   0 + t] = m;
    o[base + 128 + t] = h;
    o[base + 256 + t] = m;
    o[base + 384 + t] = h;
    o[base + 512 + t] = l;
    o[base + 640 + t] = h;
}

/* unified bf16 tensor-core NT GEMM: acc[i,j] = sum_k A[i,k]*B[j,k] (fp32 acc)
   128x128 tile, BK=32, 8 warps (4M x 2N), warp tile 32x64, cp.async 2-stage.
   mode 0: C = acc (Scode)
   mode 1: C = (nB[col]+nA[row]) - 2*acc (cmcm dist)
   mode 2: fused per-row argmin -> packed atomicMin into amin (no C) */
__global__ void __launch_bounds__(256,2) k_tc(
    const __nv_bfloat16* __restrict__ A, const __nv_bfloat16* __restrict__ B,
    float* __restrict__ C, int Kd, int Nc,
    const float* __restrict__ nA, const float* __restrict__ nB,
    unsigned long long* __restrict__ amin, int mode)
{
    __shared__ __nv_bfloat16 As[2][128*32];
    __shared__ __nv_bfloat16 Bs[2][128*32];
    const int t = threadIdx.x;
    const int lane = t & 31, warp = t >> 5;
    const int wm = warp & 3, wn = warp >> 2;
    const int row0 = blockIdx.y*128, col0 = blockIdx.x*128;

    float acc[2][8][4];
    #pragma unroll
    for (int i=0;i<2;i++)
        #pragma unroll
        for (int n=0;n<8;n++)
            #pragma unroll
            for (int x=0;x<4;x++) acc[i][n][x] = 0.f;

    auto prefetch = [&](int kb, int buf){
        size_t k0 = (size_t)kb*32;
        int r1 = t>>2, c1 = t&3;
        int s1 = c1 ^ ((r1>>1)&3);
        cp16(&As[buf][r1*32 + s1*8], A + (size_t)(row0+r1)*Kd + k0 + c1*8);
        cp16(&Bs[buf][r1*32 + s1*8], B + (size_t)(col0+r1)*Kd + k0 + c1*8);
        int r2 = 64 + r1;
        int s2 = c1 ^ ((r2>>1)&3);
        cp16(&As[buf][r2*32 + s2*8], A + (size_t)(row0+r2)*Kd + k0 + c1*8);
        cp16(&Bs[buf][r2*32 + s2*8], B + (size_t)(col0+r2)*Kd + k0 + c1*8);
    };

    const int nKb = Kd/32;
    prefetch(0, 0);
    asm volatile("cp.async.commit_group;\n" ::);

    for (int kb=0; kb<nKb; ++kb){
        int buf = kb & 1;
        asm volatile("cp.async.wait_group 0;\n" ::);
        __syncthreads();
        if (kb+1 < nKb){
            prefetch(kb+1, buf^1);
            asm volatile("cp.async.commit_group;\n" ::);
        }
        #pragma unroll
        for (int ks=0; ks<2; ++ks){
            unsigned a[2][4];
            #pragma unroll
            for (int i=0;i<2;i++){
                int r  = wm*32 + i*16 + (lane & 15);
                int cb = ks*2 + (lane >> 4);
                ldm4(a[i][0],a[i][1],a[i][2],a[i][3],
                     &As[buf][r*32 + ((cb ^ ((r>>1)&3))<<3)]);
            }
            unsigned b[8][2];
            #pragma unroll
            for (int j=0;j<4;j++){
                int g  = lane >> 3;
                int r  = wn*64 + j*16 + (lane & 7) + ((g>>1)<<3);
                int cb = ks*2 + (g & 1);
                unsigned b0,b1,b2,b3;
                ldm4(b0,b1,b2,b3, &Bs[buf][r*32 + ((cb ^ ((r>>1)&3))<<3)]);
                b[2*j][0]=b0; b[2*j][1]=b1; b[2*j+1][0]=b2; b[2*j+1][1]=b3;
            }
            #pragma unroll
            for (int i=0;i<2;i++)
                #pragma unroll
                for (int n=0;n<8;n++)
                    mma_bf16(acc[i][n], a[i], b[n]);
        }
    }

    if (mode == 2){
        /* fused argmin: each thread owns 16 cols per row; first-index ties */
        #pragma unroll
        for (int i=0;i<2;i++){
            #pragma unroll
            for (int half=0; half<2; half++){
                int r = row0 + wm*32 + i*16 + (lane>>2) + half*8;
                float na = nA[r];
                float best = INFINITY; int bc = 0;
                #pragma unroll
                for (int n=0;n<8;n++){
                    #pragma unroll
                    for (int x=0;x<2;x++){
                        int c = col0 + wn*64 + n*8 + (lane&3)*2 + x;
                        float v = (nB[c] + na) - 2.0f*acc[i][n][half*2+x];
                        if (v < best){ best = v; bc = c; }
                    }
                }
                unsigned long long p =
                    ((unsigned long long)f2ord(best) << 32) | (unsigned)bc;
                unsigned long long q1 = __shfl_xor_sync(0xffffffffu, p, 1, 4);
                if (q1 < p) p = q1;
                unsigned long long q2 = __shfl_xor_sync(0xffffffffu, p, 2, 4);
                if (q2 < p) p = q2;
                if ((lane&3)==0) atomicMin(amin + r, p);
            }
        }
    } else if (mode == 1){
        #pragma unroll
        for (int i=0;i<2;i++){
            int r = row0 + wm*32 + i*16 + (lane>>2);
            float na  = nA[r];
            float na8 = nA[r+8];
            #pragma unroll
            for (int n=0;n<8;n++){
                int c = col0 + wn*64 + n*8 + (lane&3)*2;
                float v0 = (nB[c]   + na ) - 2.0f*acc[i][n][0];
                float v1 = (nB[c+1] + na ) - 2.0f*acc[i][n][1];
                float v2 = (nB[c]   + na8) - 2.0f*acc[i][n][2];
                float v3 = (nB[c+1] + na8) - 2.0f*acc[i][n][3];
                *(float2*)(C + (size_t)r*Nc + c)     = make_float2(v0, v1);
                *(float2*)(C + (size_t)(r+8)*Nc + c) = make_float2(v2, v3);
            }
        }
    } else {
        #pragma unroll
        for (int i=0;i<2;i++){
            int r = row0 + wm*32 + i*16 + (lane>>2);
            #pragma unroll
            for (int n=0;n<8;n++){
                int c = col0 + wn*64 + n*8 + (lane&3)*2;
                *(float2*)(C + (size_t)r*Nc + c)     = make_float2(acc[i][n][0], acc[i][n][1]);
                *(float2*)(C + (size_t)(r+8)*Nc + c) = make_float2(acc[i][n][2], acc[i][n][3]);
            }
        }
    }
}

__global__ void k_initamin(unsigned long long* a){
    int i = blockIdx.x*blockDim.x + threadIdx.x;
    if (i < 2*NB) a[i] = 0xFFFFFFFFFFFFFFFFull;
}

__global__ void k_zero(float* __restrict__ p, int n){
    int i = blockIdx.x*blockDim.x + threadIdx.x;
    if (i<n) p[i]=0.f;
}

__global__ void k_hist(const unsigned long long* __restrict__ amin, float* __restrict__ cnt){
    int s = blockIdx.y;
    int b = blockIdx.x*blockDim.x + threadIdx.x;
    int id = (int)(unsigned)(amin[s*NB + b] & 0xFFFFFFFFull);
    atomicAdd(cnt + s*NM + id, 1.0f);
}

__global__ void k_perp(const float* __restrict__ cnt, float* __restrict__ out_perp, int stage){
    int s = blockIdx.x, t = threadIdx.x;
    float acc = 0.f;
    for (int m=t;m<NM;m+=256){
        float avg = cnt[s*NM+m] * (1.0f/(float)NB);
        acc += avg * logf(avg + 1e-10f);
    }
    acc = blockAllReduceSum(acc);
    if (t==0) out_perp[stage*2 + s] = expf(-acc);
}

__global__ void k_update(const float* __restrict__ E, const unsigned long long* __restrict__ amin,
                         float* __restrict__ res, float* __restrict__ q,
                         float* __restrict__ out_sem, int stage){
    int s = blockIdx.y, b = blockIdx.x, t = threadIdx.x;
    int id = (int)(unsigned)(amin[s*NB + b] & 0xFFFFFFFFull);
    float e = E[(size_t)id*ND + t];
    size_t o = (size_t)s*NBD + (size_t)b*ND + t;
    res[o] -= e;
    q[o]   += e;
    if (t==0) out_sem[(size_t)s*NB*NK + (size_t)b*NK + stage] = (float)id;
}

/* cmcm softmax; writes bf16 concatenated/crossed ph and log(ph+1e-10) */
__global__ void k_softmax(const float* __restrict__ dist,
                          __nv_bfloat16* __restrict__ X, __nv_bfloat16* __restrict__ Y){
    int s = blockIdx.y, b = blockIdx.x, t = threadIdx.x;
    const float* row = dist + ((size_t)s*NB + b)*NM;
    float z[32];
    float mx = -INFINITY;
    #pragma unroll
    for (int i=0;i<32;i++){
        float v = row[i*256 + t];
        v = -sqrtf(fmaxf(v, 0.f));
        z[i] = v;
        mx = fmaxf(mx, v);
    }
    mx = blockAllReduceMax(mx);
    float sm = 0.f;
    #pragma unroll
    for (int i=0;i<32;i++){
        float e = expf(z[i]-mx);
        z[i] = e; sm += e;
    }
    sm = blockAllReduceSum(sm);
    __nv_bfloat16* xr = X + (size_t)b*(2*NM) + (size_t)s*NM;
    __nv_bfloat16* yr = Y + (size_t)b*(2*NM) + (size_t)(1-s)*NM;
    #pragma unroll
    for (int i=0;i<32;i++){
        int m = i*256 + t;
        float ph = z[i]/sm;
        xr[m] = __float2bfloat16(ph);
        yr[m] = __float2bfloat16(logf(ph + 1e-10f));
    }
}

__global__ void k_minred(const float* __restrict__ S, unsigned* mo){
    size_t NN = (size_t)NB*NB;
    float best = INFINITY;
    for (size_t n = (size_t)blockIdx.x*blockDim.x + threadIdx.x; n < NN;
         n += (size_t)gridDim.x*blockDim.x)
        best = fminf(best, S[n]);
    __shared__ float sh[256];
    sh[threadIdx.x]=best; __syncthreads();
    for (int o=128;o>0;o>>=1){
        if (threadIdx.x<o) sh[threadIdx.x]=fminf(sh[threadIdx.x],sh[threadIdx.x+o]);
        __syncthreads();
    }
    if (threadIdx.x==0) atomicMin(mo, f2ord(sh[0]));
}

__global__ void k_ratio(const float* __restrict__ S, const unsigned* mo, float* lr){
    int i = blockIdx.x, t = threadIdx.x;
    float Max = -ord2f(*mo);
    const float* row = S + (size_t)i*NB;
    float sm = 0.f;
    for (int j=t;j<NB;j+=256) sm += expf(row[j] + Max);
    sm = blockAllReduceSum(sm);
    if (t==0){
        float diag = expf(row[i] + Max);
        float ratio = diag / (sm + 1e-5f);
        atomicAdd(lr, logf(ratio));
    }
}

__global__ void k_msequant(const float* __restrict__ pcf, const float* __restrict__ plm,
                           const float* __restrict__ q, float* __restrict__ out,
                           float* mse){
    int n = blockIdx.x*blockDim.x + threadIdx.x;
    float p  = pcf[n], pl = plm[n];
    float qp = q[n],   ql = q[NBD + n];
    float qzp = p  + (qp - p);
    float qzl = pl + (ql - pl);
    out[n]        = qzp;
    out[NBD + n]  = qzl;
    float d0 = p - qzp, d1 = p - qzl, d2 = pl - qzl, d3 = pl - qzp;
    float s0 = blockAllReduceSum(d0*d0);
    float s1 = blockAllReduceSum(d1*d1);
    float s2 = blockAllReduceSum(d2*d2);
    float s3 = blockAllReduceSum(d3*d3);
    if (threadIdx.x==0){
        atomicAdd(mse+0, s0); atomicAdd(mse+1, s1);
        atomicAdd(mse+2, s2); atomicAdd(mse+3, s3);
    }
}

__global__ void k_final(const float* lr, const float* mse, float* out_loss){
    float Lc = -(*lr) / (float)NB;
    float inv = 1.0f/(float)NBD;
    float pcf_loss = 0.25f*2.0f*(mse[0]*inv) + 0.25f*(mse[1]*inv);
    float plm_loss = 0.25f*2.0f*(mse[2]*inv) + 0.25f*(mse[3]*inv);
    *out_loss = 0.5f*Lc + pcf_loss + plm_loss;
}

/* ------------------------------------------------------------------ */
extern "C" void kernel_launch(void* const* d_in, const int* in_sizes, int n_in,
                              void* d_out, int out_size){
    const float* pcf = (const float*)d_in[0];
    const float* plm = (const float*)d_in[1];
    const float* emb = (const float*)d_in[2];
    float* out = (float*)d_out;

    void *p;
    float *res,*q,*normX,*normE,*dist,*S,*cnt,*lr,*mse;
    __nv_bfloat16 *Xb,*Yb,*Eb,*Xp;
    unsigned long long* amin;
    unsigned* mo;
    cudaGetSymbolAddress(&p, g_res);   res  = (float*)p;
    cudaGetSymbolAddress(&p, g_q);     q    = (float*)p;
    cudaGetSymbolAddress(&p, g_normX); normX= (float*)p;
    cudaGetSymbolAddress(&p, g_normE); normE= (float*)p;
    cudaGetSymbolAddress(&p, g_dist);  dist = (float*)p;
    cudaGetSymbolAddress(&p, g_Eb);    Eb   = (__nv_bfloat16*)p;
    cudaGetSymbolAddress(&p, g_Xp);    Xp   = (__nv_bfloat16*)p;
    cudaGetSymbolAddress(&p, g_Xb);    Xb   = (__nv_bfloat16*)p;
    cudaGetSymbolAddress(&p, g_Yb);    Yb   = (__nv_bfloat16*)p;
    cudaGetSymbolAddress(&p, g_S);     S    = (float*)p;
    cudaGetSymbolAddress(&p, g_amin);  amin = (unsigned long long*)p;
    cudaGetSymbolAddress(&p, g_cnt);   cnt  = (float*)p;
    cudaGetSymbolAddress(&p, g_minord);mo   = (unsigned*)p;
    cudaGetSymbolAddress(&p, g_lr);    lr   = (float*)p;
    cudaGetSymbolAddress(&p, g_mse);   mse  = (float*)p;

    /* output layout: quantized [2,B,D] | loss | sem_ids [2,B,K] | perp [K,2] */
    float* out_loss = out + (size_t)2*NBD;
    float* out_sem  = out_loss + 1;
    float* out_perp = out_sem + (size_t)2*NB*NK;

    k_init<<<(2*NBD+255)/256, 256>>>(pcf, plm, res, q, mo, lr, mse);
    k_splitB<<<NK*NM, 128>>>(emb, Eb);         /* all 4 codebooks -> B-layout */
    k_rownorm<<<NK*NM, 128>>>(emb, normE);
    k_rownorm<<<NB,128>>>(pcf, normX);
    k_rownorm<<<NB,128>>>(plm, normX+NB);
    k_splitA<<<2*NB, 128>>>(res, Xp);          /* stage-0 residual = inputs */

    /* cmcm: only last stage's Lcmcm survives; uses ORIGINAL inputs + E3 */
    const __nv_bfloat16* Eb3 = Eb + (size_t)3*NM*KS6;
    k_tc<<<dim3(NM/128, NB/128), 256>>>(Xp,                  Eb3, dist,               KS6, NM, normX,    normE+3*NM, (unsigned long long*)0, 1);
    k_tc<<<dim3(NM/128, NB/128), 256>>>(Xp+(size_t)NB*KS6,   Eb3, dist+(size_t)NB*NM, KS6, NM, normX+NB, normE+3*NM, (unsigned long long*)0, 1);
    k_softmax<<<dim3(NB,2), 256>>>(dist, Xb, Yb);
    k_tc<<<dim3(NB/128, NB/128), 256>>>(Xb, Yb, S, 2*NM, NB, (const float*)0, (const float*)0, (unsigned long long*)0, 0);

    /* residual VQ stages: 6-term split bf16 dist GEMM with fused argmin */
    for (int st=0; st<NK; ++st){
        const float* E = emb + (size_t)st*NM*ND;
        const __nv_bfloat16* Ebs = Eb + (size_t)st*NM*KS6;
        if (st > 0){
            k_rownorm<<<NB,128>>>(res,      normX);
            k_rownorm<<<NB,128>>>(res+NBD,  normX+NB);
            k_splitA<<<2*NB, 128>>>(res, Xp);
        }
        k_initamin<<<(2*NB+255)/256, 256>>>(amin);
        k_tc<<<dim3(NM/128, NB/128), 256>>>(Xp,                Ebs, (float*)0, KS6, NM, normX,    normE+st*NM, amin,    2);
        k_tc<<<dim3(NM/128, NB/128), 256>>>(Xp+(size_t)NB*KS6, Ebs, (float*)0, KS6, NM, normX+NB, normE+st*NM, amin+NB, 2);
        k_zero<<<(2*NM+255)/256,256>>>(cnt, 2*NM);
        k_hist<<<dim3(NB/256,2),256>>>(amin, cnt);
        k_perp<<<2,256>>>(cnt, out_perp, st);
        k_update<<<dim3(NB,2),128>>>(E, amin, res, q, out_sem, st);
    }

    /* cmcm loss reductions */
    k_minred<<<4096,256>>>(S, mo);
    k_ratio<<<NB,256>>>(S, mo, lr);
    k_msequant<<<NBD/256,256>>>(pcf, plm, q, out, mse);
    k_final<<<1,1>>>(lr, mse, out_loss);
}